// round 6
// baseline (speedup 1.0000x reference)
#include <cuda_runtime.h>
#include <cstddef>

#define NUM_USERS 200000
#define NUM_ITEMS 100000
#define N_NODES   (NUM_USERS + NUM_ITEMS)
#define DIM       64
#define NNZ       4000000

#define SCAN_TPB  1024
#define NB_SCAN   ((N_NODES + SCAN_TPB - 1) / SCAN_TPB)   // 293

// Scratch (allocation in kernel_launch is forbidden).
__device__ float g_bufA[(size_t)N_NODES * DIM];
__device__ float g_bufB[(size_t)N_NODES * DIM];
__device__ int   g_rows_s[NNZ];
__device__ int   g_cols_s[NNZ];
__device__ float g_vals_s[NNZ];
__device__ int   g_cnt[N_NODES];      // histogram of cols
__device__ int   g_base[N_NODES];     // per-element exclusive scan within block
__device__ int   g_cursor[N_NODES];   // running cursor for permute scatter
__device__ int   g_blk_sums[NB_SCAN];
__device__ int   g_blk_off[NB_SCAN];

// ---------------------------------------------------------------------------
// init: cur = concat(user_emb, item_emb); out = 0.25 * cur (layer-0 term);
//       nxt = 0 (scatter target for layer 1)
// ---------------------------------------------------------------------------
__global__ void init_kernel(const float* __restrict__ ue,
                            const float* __restrict__ ie,
                            float* __restrict__ cur,
                            float* __restrict__ nxt,
                            float* __restrict__ out) {
    size_t i = (size_t)blockIdx.x * blockDim.x + threadIdx.x;   // float4 index
    const size_t total = (size_t)N_NODES * DIM / 4;
    if (i >= total) return;
    const size_t uf4 = (size_t)NUM_USERS * DIM / 4;
    float4 v;
    if (i < uf4) v = ((const float4*)ue)[i];
    else         v = ((const float4*)ie)[i - uf4];
    ((float4*)cur)[i] = v;
    ((float4*)out)[i] = make_float4(0.25f * v.x, 0.25f * v.y,
                                    0.25f * v.z, 0.25f * v.w);
    ((float4*)nxt)[i] = make_float4(0.f, 0.f, 0.f, 0.f);
}

// ---------------------------------------------------------------------------
// counting-sort-by-col pipeline
// ---------------------------------------------------------------------------
__global__ void zero_counters_kernel(int* __restrict__ cnt,
                                     int* __restrict__ cursor) {
    int i = blockIdx.x * blockDim.x + threadIdx.x;
    if (i < N_NODES) { cnt[i] = 0; cursor[i] = 0; }
}

__global__ void hist_kernel(const int* __restrict__ cols,
                            int* __restrict__ cnt) {
    int e = blockIdx.x * blockDim.x + threadIdx.x;
    if (e < NNZ) atomicAdd(&cnt[cols[e]], 1);
}

// Exclusive scan within each 1024-block; emit block totals.
__global__ void scan1_kernel(const int* __restrict__ cnt,
                             int* __restrict__ base,
                             int* __restrict__ blk_sums) {
    __shared__ int s[SCAN_TPB];
    int i = blockIdx.x * SCAN_TPB + threadIdx.x;
    int v = (i < N_NODES) ? cnt[i] : 0;
    s[threadIdx.x] = v;
    __syncthreads();
    for (int off = 1; off < SCAN_TPB; off <<= 1) {
        int t = (threadIdx.x >= off) ? s[threadIdx.x - off] : 0;
        __syncthreads();
        s[threadIdx.x] += t;
        __syncthreads();
    }
    if (i < N_NODES) base[i] = s[threadIdx.x] - v;   // exclusive
    if (threadIdx.x == SCAN_TPB - 1) blk_sums[blockIdx.x] = s[SCAN_TPB - 1];
}

// Exclusive scan over NB_SCAN (<=512) block sums in one block.
__global__ void scan2_kernel(const int* __restrict__ blk_sums,
                             int* __restrict__ blk_off) {
    __shared__ int s[512];
    int i = threadIdx.x;
    int v = (i < NB_SCAN) ? blk_sums[i] : 0;
    s[i] = v;
    __syncthreads();
    for (int off = 1; off < 512; off <<= 1) {
        int t = (i >= off) ? s[i - off] : 0;
        __syncthreads();
        s[i] += t;
        __syncthreads();
    }
    if (i < NB_SCAN) blk_off[i] = s[i] - v;          // exclusive
}

// Permute edges into col-sorted order.
__global__ void scatter_sort_kernel(const float* __restrict__ vals,
                                    const int*   __restrict__ rows,
                                    const int*   __restrict__ cols,
                                    const int*   __restrict__ base,
                                    const int*   __restrict__ blk_off,
                                    int*         __restrict__ cursor,
                                    int*   __restrict__ rows_s,
                                    int*   __restrict__ cols_s,
                                    float* __restrict__ vals_s) {
    int e = blockIdx.x * blockDim.x + threadIdx.x;
    if (e >= NNZ) return;
    int c = cols[e];
    int p = base[c] + blk_off[c >> 10] + atomicAdd(&cursor[c], 1);
    rows_s[p] = rows[e];
    cols_s[p] = c;
    vals_s[p] = vals[e];
}

// ---------------------------------------------------------------------------
// spmm on col-sorted edges: y[rows[e]] += vals[e] * x[cols[e]]
// 16 threads per edge, float4 each. Consecutive edges share cols -> gather
// hits L1/L2 instead of DRAM.
// ---------------------------------------------------------------------------
__global__ void __launch_bounds__(256)
spmm_kernel(const float* __restrict__ vals,
            const int*   __restrict__ rows,
            const int*   __restrict__ cols,
            const float* __restrict__ x,
            float*       __restrict__ y) {
    size_t t = (size_t)blockIdx.x * blockDim.x + threadIdx.x;
    size_t e = t >> 4;          // edge index
    int    d = (int)(t & 15);   // float4 slot within the 64-float row
    if (e >= NNZ) return;
    int   r = __ldg(rows + e);
    int   c = __ldg(cols + e);
    float v = __ldg(vals + e);
    float4 xv = __ldg(((const float4*)(x + (size_t)c * DIM)) + d);
    float4 m  = make_float4(v * xv.x, v * xv.y, v * xv.z, v * xv.w);
    atomicAdd(((float4*)(y + (size_t)r * DIM)) + d, m);
}

// ---------------------------------------------------------------------------
// accum: out += 0.25 * next; also zero `dead` (scatter target for next layer)
// ---------------------------------------------------------------------------
__global__ void accum_kernel(const float* __restrict__ next,
                             float* __restrict__ out,
                             float* __restrict__ dead,
                             int    do_zero) {
    size_t i = (size_t)blockIdx.x * blockDim.x + threadIdx.x;
    if (i >= (size_t)N_NODES * DIM / 4) return;
    float4 n = ((const float4*)next)[i];
    float4 o = ((float4*)out)[i];
    o.x += 0.25f * n.x;
    o.y += 0.25f * n.y;
    o.z += 0.25f * n.z;
    o.w += 0.25f * n.w;
    ((float4*)out)[i] = o;
    if (do_zero)
        ((float4*)dead)[i] = make_float4(0.f, 0.f, 0.f, 0.f);
}

// ---------------------------------------------------------------------------
// launch
// ---------------------------------------------------------------------------
extern "C" void kernel_launch(void* const* d_in, const int* in_sizes, int n_in,
                              void* d_out, int out_size) {
    const float* ue   = (const float*)d_in[0];
    const float* ie   = (const float*)d_in[1];
    const float* vals = (const float*)d_in[2];
    const int*   rows = (const int*)d_in[3];
    const int*   cols = (const int*)d_in[4];
    float* out = (float*)d_out;

    float *bufA, *bufB, *vals_s;
    int *rows_s, *cols_s, *cnt, *base, *cursor, *blk_sums, *blk_off;
    cudaGetSymbolAddress((void**)&bufA, g_bufA);
    cudaGetSymbolAddress((void**)&bufB, g_bufB);
    cudaGetSymbolAddress((void**)&rows_s, g_rows_s);
    cudaGetSymbolAddress((void**)&cols_s, g_cols_s);
    cudaGetSymbolAddress((void**)&vals_s, g_vals_s);
    cudaGetSymbolAddress((void**)&cnt, g_cnt);
    cudaGetSymbolAddress((void**)&base, g_base);
    cudaGetSymbolAddress((void**)&cursor, g_cursor);
    cudaGetSymbolAddress((void**)&blk_sums, g_blk_sums);
    cudaGetSymbolAddress((void**)&blk_off, g_blk_off);

    const int TPB = 256;
    const size_t nf4 = (size_t)N_NODES * DIM / 4;           // 4.8M float4s
    const int grid_f4   = (int)((nf4 + TPB - 1) / TPB);
    const int grid_node = (N_NODES + TPB - 1) / TPB;
    const int grid_edge = (NNZ + TPB - 1) / TPB;
    const size_t spmm_threads = (size_t)NNZ * 16;           // 64M threads
    const int grid_spmm = (int)((spmm_threads + TPB - 1) / TPB);

    // ---- build col-sorted edge list (amortized over 3 layers) ----
    zero_counters_kernel<<<grid_node, TPB>>>(cnt, cursor);
    hist_kernel<<<grid_edge, TPB>>>(cols, cnt);
    scan1_kernel<<<NB_SCAN, SCAN_TPB>>>(cnt, base, blk_sums);
    scan2_kernel<<<1, 512>>>(blk_sums, blk_off);
    scatter_sort_kernel<<<grid_edge, TPB>>>(vals, rows, cols, base, blk_off,
                                            cursor, rows_s, cols_s, vals_s);

    // ---- embeddings: cur = concat, out = 0.25*cur, nxt zeroed ----
    init_kernel<<<grid_f4, TPB>>>(ue, ie, bufA, bufB, out);

    float* cur = bufA;
    float* nxt = bufB;
    for (int layer = 0; layer < 3; ++layer) {
        spmm_kernel<<<grid_spmm, TPB>>>(vals_s, rows_s, cols_s, cur, nxt);
        // out += 0.25*nxt; zero `cur` so it can be the scatter target next layer
        accum_kernel<<<grid_f4, TPB>>>(nxt, out, cur, layer < 2 ? 1 : 0);
        float* tmp = cur; cur = nxt; nxt = tmp;
    }
}

// round 8
// speedup vs baseline: 1.9578x; 1.9578x over previous
#include <cuda_runtime.h>
#include <cstddef>

#define NUM_USERS 200000
#define NUM_ITEMS 100000
#define N_NODES   (NUM_USERS + NUM_ITEMS)
#define DIM       64
#define NNZ       4000000

#define SCAN_TPB  1024
#define NB_SCAN   ((N_NODES + SCAN_TPB - 1) / SCAN_TPB)   // 293

// Scratch (allocation in kernel_launch is forbidden).
__device__ float g_bufA[(size_t)N_NODES * DIM];
__device__ float g_bufB[(size_t)N_NODES * DIM];
__device__ int   g_cols_s[NNZ];       // cols, sorted by row
__device__ float g_vals_s[NNZ];       // vals, sorted by row
__device__ int   g_cnt[N_NODES];      // histogram of rows
__device__ int   g_base[N_NODES];     // within-block exclusive scan
__device__ int   g_row_ptr[N_NODES + 1];
__device__ int   g_cursor[N_NODES];   // running cursor for permute scatter
__device__ int   g_blk_sums[NB_SCAN];
__device__ int   g_blk_off[NB_SCAN];

// ---------------------------------------------------------------------------
// init: cur = concat(user_emb, item_emb); out = 0.25 * cur (layer-0 term)
// ---------------------------------------------------------------------------
__global__ void init_kernel(const float* __restrict__ ue,
                            const float* __restrict__ ie,
                            float* __restrict__ cur,
                            float* __restrict__ out) {
    size_t i = (size_t)blockIdx.x * blockDim.x + threadIdx.x;   // float4 index
    const size_t total = (size_t)N_NODES * DIM / 4;
    if (i >= total) return;
    const size_t uf4 = (size_t)NUM_USERS * DIM / 4;
    float4 v;
    if (i < uf4) v = ((const float4*)ue)[i];
    else         v = ((const float4*)ie)[i - uf4];
    ((float4*)cur)[i] = v;
    ((float4*)out)[i] = make_float4(0.25f * v.x, 0.25f * v.y,
                                    0.25f * v.z, 0.25f * v.w);
}

// ---------------------------------------------------------------------------
// CSR build: counting sort of edges by row
// ---------------------------------------------------------------------------
__global__ void zero_counters_kernel(int* __restrict__ cnt,
                                     int* __restrict__ cursor) {
    int i = blockIdx.x * blockDim.x + threadIdx.x;
    if (i < N_NODES) { cnt[i] = 0; cursor[i] = 0; }
}

__global__ void hist_kernel(const int* __restrict__ rows,
                            int* __restrict__ cnt) {
    int e = blockIdx.x * blockDim.x + threadIdx.x;
    if (e < NNZ) atomicAdd(&cnt[rows[e]], 1);
}

// Exclusive scan within each 1024-block; emit block totals.
__global__ void scan1_kernel(const int* __restrict__ cnt,
                             int* __restrict__ base,
                             int* __restrict__ blk_sums) {
    __shared__ int s[SCAN_TPB];
    int i = blockIdx.x * SCAN_TPB + threadIdx.x;
    int v = (i < N_NODES) ? cnt[i] : 0;
    s[threadIdx.x] = v;
    __syncthreads();
    for (int off = 1; off < SCAN_TPB; off <<= 1) {
        int t = (threadIdx.x >= off) ? s[threadIdx.x - off] : 0;
        __syncthreads();
        s[threadIdx.x] += t;
        __syncthreads();
    }
    if (i < N_NODES) base[i] = s[threadIdx.x] - v;   // exclusive
    if (threadIdx.x == SCAN_TPB - 1) blk_sums[blockIdx.x] = s[SCAN_TPB - 1];
}

// Exclusive scan over NB_SCAN (<=512) block sums in one block.
__global__ void scan2_kernel(const int* __restrict__ blk_sums,
                             int* __restrict__ blk_off) {
    __shared__ int s[512];
    int i = threadIdx.x;
    int v = (i < NB_SCAN) ? blk_sums[i] : 0;
    s[i] = v;
    __syncthreads();
    for (int off = 1; off < 512; off <<= 1) {
        int t = (i >= off) ? s[i - off] : 0;
        __syncthreads();
        s[i] += t;
        __syncthreads();
    }
    if (i < NB_SCAN) blk_off[i] = s[i] - v;          // exclusive
}

// row_ptr[i] = base[i] + blk_off[i>>10];  row_ptr[N_NODES] = NNZ
__global__ void rowptr_kernel(const int* __restrict__ base,
                              const int* __restrict__ blk_off,
                              int* __restrict__ row_ptr) {
    int i = blockIdx.x * blockDim.x + threadIdx.x;
    if (i < N_NODES) row_ptr[i] = base[i] + blk_off[i >> 10];
    if (i == 0)      row_ptr[N_NODES] = NNZ;
}

// Permute edges into row-sorted order (only need col & val).
__global__ void scatter_sort_kernel(const float* __restrict__ vals,
                                    const int*   __restrict__ rows,
                                    const int*   __restrict__ cols,
                                    const int*   __restrict__ row_ptr,
                                    int*         __restrict__ cursor,
                                    int*   __restrict__ cols_s,
                                    float* __restrict__ vals_s) {
    int e = blockIdx.x * blockDim.x + threadIdx.x;
    if (e >= NNZ) return;
    int r = rows[e];
    int p = row_ptr[r] + atomicAdd(&cursor[r], 1);
    cols_s[p] = cols[e];
    vals_s[p] = vals[e];
}

// ---------------------------------------------------------------------------
// spmm_csr: one warp per row. Lane l owns float2 slot l of the 64-float row.
//   acc = sum over row's edges of v * x[c]
//   nxt[r] = acc;  out[r] += 0.25 * acc   (fused accum; no atomics anywhere)
// ---------------------------------------------------------------------------
__global__ void __launch_bounds__(256)
spmm_csr_kernel(const int*   __restrict__ row_ptr,
                const int*   __restrict__ cols_s,
                const float* __restrict__ vals_s,
                const float* __restrict__ x,
                float*       __restrict__ y,
                float*       __restrict__ out) {
    int w    = (int)(((size_t)blockIdx.x * blockDim.x + threadIdx.x) >> 5);
    int lane = threadIdx.x & 31;
    if (w >= N_NODES) return;

    int s = __ldg(row_ptr + w);
    int e = __ldg(row_ptr + w + 1);

    float2 acc = make_float2(0.f, 0.f);
    int i = s;
    // 2-edge unroll for memory-level parallelism
    for (; i + 1 < e; i += 2) {
        int   c0 = __ldg(cols_s + i);
        int   c1 = __ldg(cols_s + i + 1);
        float v0 = __ldg(vals_s + i);
        float v1 = __ldg(vals_s + i + 1);
        float2 x0 = __ldg((const float2*)(x + (size_t)c0 * DIM) + lane);
        float2 x1 = __ldg((const float2*)(x + (size_t)c1 * DIM) + lane);
        acc.x += v0 * x0.x + v1 * x1.x;
        acc.y += v0 * x0.y + v1 * x1.y;
    }
    if (i < e) {
        int   c0 = __ldg(cols_s + i);
        float v0 = __ldg(vals_s + i);
        float2 x0 = __ldg((const float2*)(x + (size_t)c0 * DIM) + lane);
        acc.x += v0 * x0.x;
        acc.y += v0 * x0.y;
    }

    float2* yp = (float2*)(y + (size_t)w * DIM) + lane;
    *yp = acc;
    float2* op = (float2*)(out + (size_t)w * DIM) + lane;
    float2 o = *op;
    o.x += 0.25f * acc.x;
    o.y += 0.25f * acc.y;
    *op = o;
}

// ---------------------------------------------------------------------------
// launch
// ---------------------------------------------------------------------------
extern "C" void kernel_launch(void* const* d_in, const int* in_sizes, int n_in,
                              void* d_out, int out_size) {
    const float* ue   = (const float*)d_in[0];
    const float* ie   = (const float*)d_in[1];
    const float* vals = (const float*)d_in[2];
    const int*   rows = (const int*)d_in[3];
    const int*   cols = (const int*)d_in[4];
    float* out = (float*)d_out;

    float *bufA, *bufB, *vals_s;
    int *cols_s, *cnt, *base, *row_ptr, *cursor, *blk_sums, *blk_off;
    cudaGetSymbolAddress((void**)&bufA, g_bufA);
    cudaGetSymbolAddress((void**)&bufB, g_bufB);
    cudaGetSymbolAddress((void**)&cols_s, g_cols_s);
    cudaGetSymbolAddress((void**)&vals_s, g_vals_s);
    cudaGetSymbolAddress((void**)&cnt, g_cnt);
    cudaGetSymbolAddress((void**)&base, g_base);
    cudaGetSymbolAddress((void**)&row_ptr, g_row_ptr);
    cudaGetSymbolAddress((void**)&cursor, g_cursor);
    cudaGetSymbolAddress((void**)&blk_sums, g_blk_sums);
    cudaGetSymbolAddress((void**)&blk_off, g_blk_off);

    const int TPB = 256;
    const size_t nf4 = (size_t)N_NODES * DIM / 4;           // 4.8M float4s
    const int grid_f4   = (int)((nf4 + TPB - 1) / TPB);
    const int grid_node = (N_NODES + TPB - 1) / TPB;
    const int grid_edge = (NNZ + TPB - 1) / TPB;
    const size_t spmm_threads = (size_t)N_NODES * 32;       // warp per row
    const int grid_spmm = (int)((spmm_threads + TPB - 1) / TPB);

    // ---- build row-sorted CSR (amortized over 3 layers) ----
    zero_counters_kernel<<<grid_node, TPB>>>(cnt, cursor);
    hist_kernel<<<grid_edge, TPB>>>(rows, cnt);
    scan1_kernel<<<NB_SCAN, SCAN_TPB>>>(cnt, base, blk_sums);
    scan2_kernel<<<1, 512>>>(blk_sums, blk_off);
    rowptr_kernel<<<grid_node, TPB>>>(base, blk_off, row_ptr);
    scatter_sort_kernel<<<grid_edge, TPB>>>(vals, rows, cols, row_ptr,
                                            cursor, cols_s, vals_s);

    // ---- embeddings: cur = concat, out = 0.25*cur ----
    init_kernel<<<grid_f4, TPB>>>(ue, ie, bufA, out);

    float* cur = bufA;
    float* nxt = bufB;
    for (int layer = 0; layer < 3; ++layer) {
        spmm_csr_kernel<<<grid_spmm, TPB>>>(row_ptr, cols_s, vals_s,
                                            cur, nxt, out);
        float* tmp = cur; cur = nxt; nxt = tmp;
    }
}